// round 2
// baseline (speedup 1.0000x reference)
#include <cuda_runtime.h>
#include <cstdint>

#define NB 4096
#define ND 1024
#define F_EPS 1e-6f
#define F_MARGIN 0.3f

// ------------------------- scratch (static device globals; no allocation) ---
__device__ float g_G[(size_t)NB * NB];   // gram matrix F F^T (64 MB)
__device__ float g_t[NB];                // n2[j] + 2*eps*s[j] + D*eps^2
__device__ float g_c[NB];                // n2[i] - 2*eps*s[i]
__device__ int   g_pos[NB];
__device__ int   g_neg[NB];
__device__ float g_part[NB];             // per-row loss partial sums

// ------------------------- Threefry-2x32 (20 rounds), JAX-compatible --------
__device__ __forceinline__ uint32_t rotl_d(uint32_t x, int r) {
    return __funnelshift_l(x, x, r);
}

__device__ __forceinline__ void tf_enc(uint32_t k0, uint32_t k1,
                                       uint32_t x0, uint32_t x1,
                                       uint32_t& o0, uint32_t& o1) {
    uint32_t k2 = k0 ^ k1 ^ 0x1BD11BDAu;
    x0 += k0; x1 += k1;
#define TFR(R) { x0 += x1; x1 = rotl_d(x1, R); x1 ^= x0; }
    TFR(13) TFR(15) TFR(26) TFR(6)
    x0 += k1; x1 += k2 + 1u;
    TFR(17) TFR(29) TFR(16) TFR(24)
    x0 += k2; x1 += k0 + 2u;
    TFR(13) TFR(15) TFR(26) TFR(6)
    x0 += k0; x1 += k1 + 3u;
    TFR(17) TFR(29) TFR(16) TFR(24)
    x0 += k1; x1 += k2 + 4u;
    TFR(13) TFR(15) TFR(26) TFR(6)
    x0 += k2; x1 += k0 + 5u;
#undef TFR
    o0 = x0; o1 = x1;
}

// host copy (for computing the split keys k1, k2 of jax.random.split(key(42),3))
static inline uint32_t rotl_h(uint32_t x, int r) { return (x << r) | (x >> (32 - r)); }
static void tf_enc_host(uint32_t k0, uint32_t k1, uint32_t x0, uint32_t x1,
                        uint32_t& o0, uint32_t& o1) {
    uint32_t k2 = k0 ^ k1 ^ 0x1BD11BDAu;
    x0 += k0; x1 += k1;
#define TFRH(R) { x0 += x1; x1 = rotl_h(x1, R); x1 ^= x0; }
    TFRH(13) TFRH(15) TFRH(26) TFRH(6)
    x0 += k1; x1 += k2 + 1u;
    TFRH(17) TFRH(29) TFRH(16) TFRH(24)
    x0 += k2; x1 += k0 + 2u;
    TFRH(13) TFRH(15) TFRH(26) TFRH(6)
    x0 += k0; x1 += k1 + 3u;
    TFRH(17) TFRH(29) TFRH(16) TFRH(24)
    x0 += k1; x1 += k2 + 4u;
    TFRH(13) TFRH(15) TFRH(26) TFRH(6)
    x0 += k2; x1 += k0 + 5u;
#undef TFRH
    o0 = x0; o1 = x1;
}

// ------------------------- sampling kernel ----------------------------------
// partitionable threefry: bits[m] = w0 ^ w1 of E_key(0, m), m = i*4096 + j.
// argmax over masked uniforms == integer argmax over (bits>>9), first-index ties.
__global__ void __launch_bounds__(256) k_sample(const int* __restrict__ labels,
                                                uint32_t k1a, uint32_t k1b,
                                                uint32_t k2a, uint32_t k2b) {
    __shared__ int slab[NB];
    __shared__ unsigned long long redn[8], redp[8];
    const int i = blockIdx.x;
    for (int t = threadIdx.x * 4; t < NB; t += blockDim.x * 4)
        *(int4*)&slab[t] = *(const int4*)&labels[t];
    __syncthreads();
    const int Li = slab[i];
    const uint32_t base = (uint32_t)i << 12;

    unsigned long long bestn = 0ull, bestp = 0ull;
    for (int j = threadIdx.x; j < NB; j += blockDim.x) {
        uint32_t o0, o1;
        tf_enc(k2a, k2b, 0u, base + (uint32_t)j, o0, o1);
        uint32_t v = ((o0 ^ o1) >> 9) + 1u;                       // 1..2^23
        unsigned long long cand =
            ((unsigned long long)v << 12) | (uint32_t)(4095 - j); // max v, min j
        if (slab[j] != Li) {
            if (cand > bestn) bestn = cand;
        } else {
            uint32_t p0, p1;
            tf_enc(k1a, k1b, 0u, base + (uint32_t)j, p0, p1);
            uint32_t vp = ((p0 ^ p1) >> 9) + 1u;
            unsigned long long candp =
                ((unsigned long long)vp << 12) | (uint32_t)(4095 - j);
            if (candp > bestp) bestp = candp;
        }
    }
    // warp reduce
    for (int off = 16; off; off >>= 1) {
        unsigned long long a = __shfl_down_sync(0xffffffffu, bestn, off);
        unsigned long long b = __shfl_down_sync(0xffffffffu, bestp, off);
        if (a > bestn) bestn = a;
        if (b > bestp) bestp = b;
    }
    const int warp = threadIdx.x >> 5, lane = threadIdx.x & 31;
    if (lane == 0) { redn[warp] = bestn; redp[warp] = bestp; }
    __syncthreads();
    if (threadIdx.x == 0) {
        unsigned long long bn = 0ull, bp = 0ull;
        for (int w = 0; w < 8; w++) {
            if (redn[w] > bn) bn = redn[w];
            if (redp[w] > bp) bp = redp[w];
        }
        g_neg[i] = 4095 - (int)(bn & 0xFFFu);
        g_pos[i] = 4095 - (int)(bp & 0xFFFu);
    }
}

// ------------------------- row norms / sums ---------------------------------
__global__ void __launch_bounds__(256) k_norms(const float* __restrict__ F) {
    const int i = blockIdx.x;
    const float4* row = (const float4*)(F + (size_t)i * ND);
    float n2 = 0.f, s = 0.f;
    for (int k = threadIdx.x; k < ND / 4; k += blockDim.x) {
        float4 v = row[k];
        n2 = fmaf(v.x, v.x, fmaf(v.y, v.y, fmaf(v.z, v.z, fmaf(v.w, v.w, n2))));
        s += (v.x + v.y) + (v.z + v.w);
    }
    for (int off = 16; off; off >>= 1) {
        n2 += __shfl_down_sync(0xffffffffu, n2, off);
        s  += __shfl_down_sync(0xffffffffu, s,  off);
    }
    __shared__ float sn[8], ss[8];
    const int warp = threadIdx.x >> 5, lane = threadIdx.x & 31;
    if (lane == 0) { sn[warp] = n2; ss[warp] = s; }
    __syncthreads();
    if (threadIdx.x == 0) {
        float a = 0.f, b = 0.f;
        for (int w = 0; w < 8; w++) { a += sn[w]; b += ss[w]; }
        g_t[i] = a + 2.f * F_EPS * b + (float)ND * F_EPS * F_EPS;
        g_c[i] = a - 2.f * F_EPS * b;
    }
}

// ------------------------- symmetric SGEMM: G = F F^T -----------------------
__global__ void __launch_bounds__(256) k_gemm(const float* __restrict__ F) {
    const int bx = blockIdx.x, by = blockIdx.y;
    if (by > bx) return;  // lower triangle + diagonal; mirror-write the rest
    __shared__ float As[16][128 + 4];
    __shared__ float Bs[16][128 + 4];
    float acc[8][8];
#pragma unroll
    for (int m = 0; m < 8; m++)
#pragma unroll
        for (int n = 0; n < 8; n++) acc[m][n] = 0.f;

    const int tid = threadIdx.x;
    const int tx = (tid & 15) << 3;
    const int ty = (tid >> 4) << 3;
    const float* Abase = F + (size_t)bx * 128 * ND;
    const float* Bbase = F + (size_t)by * 128 * ND;

    for (int kt = 0; kt < ND; kt += 16) {
#pragma unroll
        for (int l = 0; l < 2; l++) {
            int idx = tid + (l << 8);
            int r = idx >> 2;
            int cg = (idx & 3) << 2;
            float4 a = *(const float4*)(Abase + (size_t)r * ND + kt + cg);
            As[cg + 0][r] = a.x; As[cg + 1][r] = a.y;
            As[cg + 2][r] = a.z; As[cg + 3][r] = a.w;
            float4 b = *(const float4*)(Bbase + (size_t)r * ND + kt + cg);
            Bs[cg + 0][r] = b.x; Bs[cg + 1][r] = b.y;
            Bs[cg + 2][r] = b.z; Bs[cg + 3][r] = b.w;
        }
        __syncthreads();
#pragma unroll
        for (int k = 0; k < 16; k++) {
            float ar[8], br[8];
#pragma unroll
            for (int m = 0; m < 8; m++) ar[m] = As[k][ty + m];
#pragma unroll
            for (int n = 0; n < 8; n++) br[n] = Bs[k][tx + n];
#pragma unroll
            for (int m = 0; m < 8; m++)
#pragma unroll
                for (int n = 0; n < 8; n++)
                    acc[m][n] = fmaf(ar[m], br[n], acc[m][n]);
        }
        __syncthreads();
    }
    const int r0 = bx * 128 + ty, c0 = by * 128 + tx;
#pragma unroll
    for (int m = 0; m < 8; m++) {
        float4 v0 = make_float4(acc[m][0], acc[m][1], acc[m][2], acc[m][3]);
        float4 v1 = make_float4(acc[m][4], acc[m][5], acc[m][6], acc[m][7]);
        *(float4*)&g_G[(size_t)(r0 + m) * NB + c0]     = v0;
        *(float4*)&g_G[(size_t)(r0 + m) * NB + c0 + 4] = v1;
    }
    if (bx != by) {
#pragma unroll
        for (int n = 0; n < 8; n++)
#pragma unroll
            for (int m = 0; m < 8; m++)
                g_G[(size_t)(c0 + n) * NB + (r0 + m)] = acc[m][n];
    }
}

// ------------------------- loss reduction -----------------------------------
__device__ __forceinline__ float pairterm(float t, float gp, float gq,
                                          float cp, float cq) {
    float sap = fmaxf(fmaf(-2.f, gp, t + cp), 1e-12f);
    float san = fmaxf(fmaf(-2.f, gq, t + cq), 1e-12f);
    float dap, dan;
    asm("sqrt.approx.f32 %0, %1;" : "=f"(dap) : "f"(sap));
    asm("sqrt.approx.f32 %0, %1;" : "=f"(dan) : "f"(san));
    return fmaxf(dap - dan + F_MARGIN, 0.f);
}

__global__ void __launch_bounds__(256) k_loss() {
    const int i = blockIdx.x;
    const int p = g_pos[i], q = g_neg[i];
    const float cp = g_c[p], cq = g_c[q];
    const float4* Gp = (const float4*)(g_G + (size_t)p * NB);
    const float4* Gq = (const float4*)(g_G + (size_t)q * NB);
    const float4* T  = (const float4*)g_t;
    float acc = 0.f;
    for (int j = threadIdx.x; j < NB / 4; j += blockDim.x) {
        float4 gp = Gp[j], gq = Gq[j], tt = T[j];
        acc += pairterm(tt.x, gp.x, gq.x, cp, cq);
        acc += pairterm(tt.y, gp.y, gq.y, cp, cq);
        acc += pairterm(tt.z, gp.z, gq.z, cp, cq);
        acc += pairterm(tt.w, gp.w, gq.w, cp, cq);
    }
    for (int off = 16; off; off >>= 1)
        acc += __shfl_down_sync(0xffffffffu, acc, off);
    __shared__ float sa[8];
    const int warp = threadIdx.x >> 5, lane = threadIdx.x & 31;
    if (lane == 0) sa[warp] = acc;
    __syncthreads();
    if (threadIdx.x == 0) {
        float s = 0.f;
        for (int w = 0; w < 8; w++) s += sa[w];
        g_part[i] = s;
    }
}

__global__ void __launch_bounds__(256) k_final(float* __restrict__ out) {
    __shared__ double sm[256];
    double a = 0.0;
    for (int i = threadIdx.x; i < NB; i += 256) a += (double)g_part[i];
    sm[threadIdx.x] = a;
    __syncthreads();
    for (int s = 128; s; s >>= 1) {
        if (threadIdx.x < s) sm[threadIdx.x] += sm[threadIdx.x + s];
        __syncthreads();
    }
    if (threadIdx.x == 0)
        out[0] = (float)(sm[0] / (double)((size_t)NB * NB));
}

// ------------------------- launch -------------------------------------------
extern "C" void kernel_launch(void* const* d_in, const int* in_sizes, int n_in,
                              void* d_out, int out_size) {
    const float* F = (const float*)d_in[0];
    const int* labels = (const int*)d_in[1];
    float* out = (float*)d_out;

    // jax.random.split(key(42), 3), partitionable: k_i = E_{(0,42)}(0, i)
    uint32_t k1a, k1b, k2a, k2b;
    tf_enc_host(0u, 42u, 0u, 0u, k1a, k1b);
    tf_enc_host(0u, 42u, 0u, 1u, k2a, k2b);
    // k3 (randint fallback) is dead: every row has a negative.

    k_sample<<<NB, 256>>>(labels, k1a, k1b, k2a, k2b);
    k_norms<<<NB, 256>>>(F);
    dim3 g(32, 32);
    k_gemm<<<g, 256>>>(F);
    k_loss<<<NB, 256>>>();
    k_final<<<1, 256>>>(out);
}

// round 5
// speedup vs baseline: 1.3563x; 1.3563x over previous
#include <cuda_runtime.h>
#include <cuda_bf16.h>
#include <cstdint>

#define NB 4096
#define ND 1024
#define F_EPS 1e-6f
#define F_MARGIN 0.3f

// ------------------------- scratch (static device globals; no allocation) ---
__device__ float g_G[(size_t)NB * NB];   // gram matrix F F^T (64 MB)
__device__ float g_t[NB];
__device__ float g_c[NB];
__device__ int   g_pos[NB];
__device__ int   g_neg[NB];
__device__ float g_part[NB];
__device__ __align__(16) uint16_t g_hi[(size_t)NB * ND];  // bf16 hi
__device__ __align__(16) uint16_t g_lo[(size_t)NB * ND];  // bf16 lo

// ------------------------- Threefry-2x32 (20 rounds), JAX-compatible --------
__device__ __forceinline__ uint32_t rotl_d(uint32_t x, int r) {
    return __funnelshift_l(x, x, r);
}
__device__ __forceinline__ void tf_enc(uint32_t k0, uint32_t k1,
                                       uint32_t x0, uint32_t x1,
                                       uint32_t& o0, uint32_t& o1) {
    uint32_t k2 = k0 ^ k1 ^ 0x1BD11BDAu;
    x0 += k0; x1 += k1;
#define TFR(R) { x0 += x1; x1 = rotl_d(x1, R); x1 ^= x0; }
    TFR(13) TFR(15) TFR(26) TFR(6)
    x0 += k1; x1 += k2 + 1u;
    TFR(17) TFR(29) TFR(16) TFR(24)
    x0 += k2; x1 += k0 + 2u;
    TFR(13) TFR(15) TFR(26) TFR(6)
    x0 += k0; x1 += k1 + 3u;
    TFR(17) TFR(29) TFR(16) TFR(24)
    x0 += k1; x1 += k2 + 4u;
    TFR(13) TFR(15) TFR(26) TFR(6)
    x0 += k2; x1 += k0 + 5u;
#undef TFR
    o0 = x0; o1 = x1;
}
static inline uint32_t rotl_h(uint32_t x, int r) { return (x << r) | (x >> (32 - r)); }
static void tf_enc_host(uint32_t k0, uint32_t k1, uint32_t x0, uint32_t x1,
                        uint32_t& o0, uint32_t& o1) {
    uint32_t k2 = k0 ^ k1 ^ 0x1BD11BDAu;
    x0 += k0; x1 += k1;
#define TFRH(R) { x0 += x1; x1 = rotl_h(x1, R); x1 ^= x0; }
    TFRH(13) TFRH(15) TFRH(26) TFRH(6)
    x0 += k1; x1 += k2 + 1u;
    TFRH(17) TFRH(29) TFRH(16) TFRH(24)
    x0 += k2; x1 += k0 + 2u;
    TFRH(13) TFRH(15) TFRH(26) TFRH(6)
    x0 += k0; x1 += k1 + 3u;
    TFRH(17) TFRH(29) TFRH(16) TFRH(24)
    x0 += k1; x1 += k2 + 4u;
    TFRH(13) TFRH(15) TFRH(26) TFRH(6)
    x0 += k2; x1 += k0 + 5u;
#undef TFRH
    o0 = x0; o1 = x1;
}

// ------------------------- sampling kernel ----------------------------------
__global__ void __launch_bounds__(256) k_sample(const int* __restrict__ labels,
                                                uint32_t k1a, uint32_t k1b,
                                                uint32_t k2a, uint32_t k2b) {
    __shared__ int slab[NB];
    __shared__ unsigned long long redn[8], redp[8];
    const int i = blockIdx.x;
    for (int t = threadIdx.x * 4; t < NB; t += blockDim.x * 4)
        *(int4*)&slab[t] = *(const int4*)&labels[t];
    __syncthreads();
    const int Li = slab[i];
    const uint32_t base = (uint32_t)i << 12;

    unsigned long long bestn = 0ull, bestp = 0ull;
    for (int j = threadIdx.x; j < NB; j += blockDim.x) {
        uint32_t o0, o1;
        tf_enc(k2a, k2b, 0u, base + (uint32_t)j, o0, o1);
        uint32_t v = ((o0 ^ o1) >> 9) + 1u;
        unsigned long long cand =
            ((unsigned long long)v << 12) | (uint32_t)(4095 - j);
        if (slab[j] != Li) {
            if (cand > bestn) bestn = cand;
        } else {
            uint32_t p0, p1;
            tf_enc(k1a, k1b, 0u, base + (uint32_t)j, p0, p1);
            uint32_t vp = ((p0 ^ p1) >> 9) + 1u;
            unsigned long long candp =
                ((unsigned long long)vp << 12) | (uint32_t)(4095 - j);
            if (candp > bestp) bestp = candp;
        }
    }
    for (int off = 16; off; off >>= 1) {
        unsigned long long a = __shfl_down_sync(0xffffffffu, bestn, off);
        unsigned long long b = __shfl_down_sync(0xffffffffu, bestp, off);
        if (a > bestn) bestn = a;
        if (b > bestp) bestp = b;
    }
    const int warp = threadIdx.x >> 5, lane = threadIdx.x & 31;
    if (lane == 0) { redn[warp] = bestn; redp[warp] = bestp; }
    __syncthreads();
    if (threadIdx.x == 0) {
        unsigned long long bn = 0ull, bp = 0ull;
        for (int w = 0; w < 8; w++) {
            if (redn[w] > bn) bn = redn[w];
            if (redp[w] > bp) bp = redp[w];
        }
        g_neg[i] = 4095 - (int)(bn & 0xFFFu);
        g_pos[i] = 4095 - (int)(bp & 0xFFFu);
    }
}

// ------------------------- row norms / sums ---------------------------------
__global__ void __launch_bounds__(256) k_norms(const float* __restrict__ F) {
    const int i = blockIdx.x;
    const float4* row = (const float4*)(F + (size_t)i * ND);
    float n2 = 0.f, s = 0.f;
    for (int k = threadIdx.x; k < ND / 4; k += blockDim.x) {
        float4 v = row[k];
        n2 = fmaf(v.x, v.x, fmaf(v.y, v.y, fmaf(v.z, v.z, fmaf(v.w, v.w, n2))));
        s += (v.x + v.y) + (v.z + v.w);
    }
    for (int off = 16; off; off >>= 1) {
        n2 += __shfl_down_sync(0xffffffffu, n2, off);
        s  += __shfl_down_sync(0xffffffffu, s,  off);
    }
    __shared__ float sn[8], ss[8];
    const int warp = threadIdx.x >> 5, lane = threadIdx.x & 31;
    if (lane == 0) { sn[warp] = n2; ss[warp] = s; }
    __syncthreads();
    if (threadIdx.x == 0) {
        float a = 0.f, b = 0.f;
        for (int w = 0; w < 8; w++) { a += sn[w]; b += ss[w]; }
        g_t[i] = a + 2.f * F_EPS * b + (float)ND * F_EPS * F_EPS;
        g_c[i] = a - 2.f * F_EPS * b;
    }
}

// ------------------------- bf16 hi/lo split (row-major) ---------------------
__global__ void __launch_bounds__(256) k_split(const float* __restrict__ F) {
    const int idx = blockIdx.x * 256 + threadIdx.x;   // 0..524287, 8 floats each
    const size_t e0 = (size_t)idx * 8;
    const float4* src = (const float4*)(F + e0);
    float4 v0 = src[0], v1 = src[1];
    float x[8] = {v0.x, v0.y, v0.z, v0.w, v1.x, v1.y, v1.z, v1.w};
    uint16_t h[8], l[8];
#pragma unroll
    for (int e = 0; e < 8; e++) {
        __nv_bfloat16 hb = __float2bfloat16(x[e]);
        __nv_bfloat16 lb = __float2bfloat16(x[e] - __bfloat162float(hb));
        h[e] = *(uint16_t*)&hb;
        l[e] = *(uint16_t*)&lb;
    }
    *(uint4*)(g_hi + e0) = *(const uint4*)h;
    *(uint4*)(g_lo + e0) = *(const uint4*)l;
}

// ------------------------- mma.sync GEMM helpers ----------------------------
__device__ __forceinline__ uint32_t smem_u32(const void* p) {
    uint32_t a;
    asm("{ .reg .u64 t; cvta.to.shared.u64 t, %1; cvt.u32.u64 %0, t; }"
        : "=r"(a) : "l"(p));
    return a;
}
#define LDSM4(r0, r1, r2, r3, addr)                                          \
    asm volatile("ldmatrix.sync.aligned.m8n8.x4.shared.b16 {%0,%1,%2,%3}, [%4];" \
                 : "=r"(r0), "=r"(r1), "=r"(r2), "=r"(r3) : "r"(addr))
#define MMA16816(c, a0, a1, a2, a3, b0, b1)                                  \
    asm volatile("mma.sync.aligned.m16n8k16.row.col.f32.bf16.bf16.f32 "      \
                 "{%0,%1,%2,%3}, {%4,%5,%6,%7}, {%8,%9}, {%0,%1,%2,%3};"     \
                 : "+f"((c)[0]), "+f"((c)[1]), "+f"((c)[2]), "+f"((c)[3])    \
                 : "r"(a0), "r"(a1), "r"(a2), "r"(a3), "r"(b0), "r"(b1))
#define CP16(saddr, gptr)                                                    \
    asm volatile("cp.async.cg.shared.global [%0], [%1], 16;"                 \
                 :: "r"(saddr), "l"(gptr) : "memory")

// smem stage layout: 4 tiles of 8192 B (Ahi, Alo, Bhi, Blo), 2 stages.
// Each tile: 128 rows x 64 B (32 bf16), 16B chunks swizzled c' = c ^ ((m>>1)&3).
#define STAGE_BYTES 32768
#define TILE_BYTES  8192

// ------------------------- tensor-core GEMM: G = F F^T ----------------------
__global__ void __launch_bounds__(256) k_gemm_mma() {
    // triangle decode: bid -> (bx, by), by <= bx
    int bid = blockIdx.x;
    int bx = (int)((sqrt(8.0 * (double)bid + 1.0) - 1.0) * 0.5);
    while ((bx + 1) * (bx + 2) / 2 <= bid) bx++;
    while (bx * (bx + 1) / 2 > bid) bx--;
    int by = bid - bx * (bx + 1) / 2;

    extern __shared__ char dsm[];
    const uint32_t smemBase = smem_u32(dsm);
    const int tid = threadIdx.x;
    const int lane = tid & 31, wid = tid >> 5;
    const int wm = wid >> 2, wn = wid & 3;   // warp tile: 64(m) x 32(n)

    // per-thread cp.async assignment: 8 chunks of 16 B
    // idx = tid + i*256 : tile = idx>>9, m = (idx>>2)&127, c = idx&3
    const uint16_t* gsrc[4];
    gsrc[0] = g_hi + (size_t)(bx * 128) * ND;
    gsrc[1] = g_lo + (size_t)(bx * 128) * ND;
    gsrc[2] = g_hi + (size_t)(by * 128) * ND;
    gsrc[3] = g_lo + (size_t)(by * 128) * ND;

    float acc[4][4][4];
#pragma unroll
    for (int a = 0; a < 4; a++)
#pragma unroll
        for (int b = 0; b < 4; b++)
#pragma unroll
            for (int c = 0; c < 4; c++) acc[a][b][c] = 0.f;

#define LOAD_STAGE(S, KT)                                                     \
    {                                                                         \
        _Pragma("unroll")                                                     \
        for (int i = 0; i < 8; i++) {                                         \
            int idx = tid + i * 256;                                          \
            int tile = idx >> 9;                                              \
            int m = (idx >> 2) & 127;                                         \
            int c = idx & 3;                                                  \
            const uint16_t* gp = gsrc[tile] + (size_t)m * ND + (KT) + c * 8;  \
            uint32_t sa = smemBase + (S) * STAGE_BYTES + tile * TILE_BYTES +  \
                          m * 64 + ((c ^ ((m >> 1) & 3)) * 16);               \
            CP16(sa, gp);                                                     \
        }                                                                     \
    }

    LOAD_STAGE(0, 0)
    asm volatile("cp.async.commit_group;" ::: "memory");

    const int r15 = lane & 15, kh = lane >> 4;

#pragma unroll 1
    for (int kc = 0; kc < 32; kc++) {
        const int buf = kc & 1;
        if (kc + 1 < 32) LOAD_STAGE((kc + 1) & 1, (kc + 1) * 32)
        asm volatile("cp.async.commit_group;" ::: "memory");
        asm volatile("cp.async.wait_group 1;" ::: "memory");
        __syncthreads();

        const uint32_t sb = smemBase + buf * STAGE_BYTES;
        const uint32_t aH = sb, aL = sb + TILE_BYTES;
        const uint32_t bH = sb + 2 * TILE_BYTES, bL = sb + 3 * TILE_BYTES;

#pragma unroll
        for (int k16 = 0; k16 < 2; k16++) {
            const int cIdx = k16 * 2 + kh;
            uint32_t bh[4][2], bl[4][2];
#pragma unroll
            for (int bt = 0; bt < 2; bt++) {
                int n = wn * 32 + bt * 16 + r15;
                uint32_t cp = (uint32_t)(cIdx ^ ((n >> 1) & 3));
                uint32_t r0, r1, r2, r3;
                LDSM4(r0, r1, r2, r3, bH + n * 64 + cp * 16);
                bh[bt * 2][0] = r0; bh[bt * 2 + 1][0] = r1;
                bh[bt * 2][1] = r2; bh[bt * 2 + 1][1] = r3;
                LDSM4(r0, r1, r2, r3, bL + n * 64 + cp * 16);
                bl[bt * 2][0] = r0; bl[bt * 2 + 1][0] = r1;
                bl[bt * 2][1] = r2; bl[bt * 2 + 1][1] = r3;
            }
#pragma unroll
            for (int mt = 0; mt < 4; mt++) {
                int m = wm * 64 + mt * 16 + r15;
                uint32_t cp = (uint32_t)(cIdx ^ ((m >> 1) & 3));
                uint32_t a0, a1, a2, a3;
                LDSM4(a0, a1, a2, a3, aH + m * 64 + cp * 16);
#pragma unroll
                for (int nt = 0; nt < 4; nt++)
                    MMA16816(acc[mt][nt], a0, a1, a2, a3, bh[nt][0], bh[nt][1]);
#pragma unroll
                for (int nt = 0; nt < 4; nt++)
                    MMA16816(acc[mt][nt], a0, a1, a2, a3, bl[nt][0], bl[nt][1]);
                LDSM4(a0, a1, a2, a3, aL + m * 64 + cp * 16);
#pragma unroll
                for (int nt = 0; nt < 4; nt++)
                    MMA16816(acc[mt][nt], a0, a1, a2, a3, bh[nt][0], bh[nt][1]);
            }
        }
        __syncthreads();
    }

    // ---------------- epilogue: direct tile + mirror via smem transpose -----
    const int r0 = bx * 128, c0 = by * 128;
    const int qr = lane >> 2, qc = 2 * (lane & 3);
#pragma unroll
    for (int mt = 0; mt < 4; mt++)
#pragma unroll
        for (int nt = 0; nt < 4; nt++) {
            int row = r0 + wm * 64 + mt * 16 + qr;
            int col = c0 + wn * 32 + nt * 8 + qc;
            float2 v01 = make_float2(acc[mt][nt][0], acc[mt][nt][1]);
            float2 v23 = make_float2(acc[mt][nt][2], acc[mt][nt][3]);
            *(float2*)&g_G[(size_t)row * NB + col] = v01;
            *(float2*)&g_G[(size_t)(row + 8) * NB + col] = v23;
        }

    if (bx != by) {
        float (*sT)[132] = (float (*)[132])dsm;   // [n][m], 128x132 floats
        __syncthreads();   // compute buffers dead; reuse smem
#pragma unroll
        for (int mt = 0; mt < 4; mt++)
#pragma unroll
            for (int nt = 0; nt < 4; nt++) {
                int rl = wm * 64 + mt * 16 + qr;
                int cl = wn * 32 + nt * 8 + qc;
                sT[cl][rl]         = acc[mt][nt][0];
                sT[cl + 1][rl]     = acc[mt][nt][1];
                sT[cl][rl + 8]     = acc[mt][nt][2];
                sT[cl + 1][rl + 8] = acc[mt][nt][3];
            }
        __syncthreads();
#pragma unroll
        for (int e = tid * 4; e < 128 * 128; e += 256 * 4) {
            int n = e >> 7, m = e & 127;
            float4 v = *(float4*)&sT[n][m];
            *(float4*)&g_G[(size_t)(c0 + n) * NB + r0 + m] = v;
        }
    }
#undef LOAD_STAGE
}

// ------------------------- loss reduction -----------------------------------
__device__ __forceinline__ float pairterm(float t, float gp, float gq,
                                          float cp, float cq) {
    float sap = fmaxf(fmaf(-2.f, gp, t + cp), 1e-12f);
    float san = fmaxf(fmaf(-2.f, gq, t + cq), 1e-12f);
    float dap, dan;
    asm("sqrt.approx.f32 %0, %1;" : "=f"(dap) : "f"(sap));
    asm("sqrt.approx.f32 %0, %1;" : "=f"(dan) : "f"(san));
    return fmaxf(dap - dan + F_MARGIN, 0.f);
}

__global__ void __launch_bounds__(256) k_loss() {
    const int i = blockIdx.x;
    const int p = g_pos[i], q = g_neg[i];
    const float cp = g_c[p], cq = g_c[q];
    const float4* Gp = (const float4*)(g_G + (size_t)p * NB);
    const float4* Gq = (const float4*)(g_G + (size_t)q * NB);
    const float4* T  = (const float4*)g_t;
    float acc = 0.f;
    for (int j = threadIdx.x; j < NB / 4; j += blockDim.x) {
        float4 gp = Gp[j], gq = Gq[j], tt = T[j];
        acc += pairterm(tt.x, gp.x, gq.x, cp, cq);
        acc += pairterm(tt.y, gp.y, gq.y, cp, cq);
        acc += pairterm(tt.z, gp.z, gq.z, cp, cq);
        acc += pairterm(tt.w, gp.w, gq.w, cp, cq);
    }
    for (int off = 16; off; off >>= 1)
        acc += __shfl_down_sync(0xffffffffu, acc, off);
    __shared__ float sa[8];
    const int warp = threadIdx.x >> 5, lane = threadIdx.x & 31;
    if (lane == 0) sa[warp] = acc;
    __syncthreads();
    if (threadIdx.x == 0) {
        float s = 0.f;
        for (int w = 0; w < 8; w++) s += sa[w];
        g_part[i] = s;
    }
}

__global__ void __launch_bounds__(256) k_final(float* __restrict__ out) {
    __shared__ double sm[256];
    double a = 0.0;
    for (int i = threadIdx.x; i < NB; i += 256) a += (double)g_part[i];
    sm[threadIdx.x] = a;
    __syncthreads();
    for (int s = 128; s; s >>= 1) {
        if (threadIdx.x < s) sm[threadIdx.x] += sm[threadIdx.x + s];
        __syncthreads();
    }
    if (threadIdx.x == 0)
        out[0] = (float)(sm[0] / (double)((size_t)NB * NB));
}

// ------------------------- launch -------------------------------------------
extern "C" void kernel_launch(void* const* d_in, const int* in_sizes, int n_in,
                              void* d_out, int out_size) {
    const float* F = (const float*)d_in[0];
    const int* labels = (const int*)d_in[1];
    float* out = (float*)d_out;

    uint32_t k1a, k1b, k2a, k2b;
    tf_enc_host(0u, 42u, 0u, 0u, k1a, k1b);
    tf_enc_host(0u, 42u, 0u, 1u, k2a, k2b);

    // dyn smem: max(2 stages = 65536, transpose 128*132*4 = 67584)
    static int smem_set = 0;
    if (!smem_set) {
        cudaFuncSetAttribute(k_gemm_mma,
                             cudaFuncAttributeMaxDynamicSharedMemorySize, 67584);
        smem_set = 1;
    }

    k_split<<<2048, 256>>>(F);
    k_sample<<<NB, 256>>>(labels, k1a, k1b, k2a, k2b);
    k_norms<<<NB, 256>>>(F);
    k_gemm_mma<<<528, 256, 67584>>>();
    k_loss<<<NB, 256>>>();
    k_final<<<1, 256>>>(out);
}

// round 7
// speedup vs baseline: 2.1268x; 1.5681x over previous
#include <cuda_runtime.h>
#include <cuda_bf16.h>
#include <cstdint>

#define NB 4096
#define ND 1024
#define F_EPS 1e-6f
#define F_MARGIN 0.3f

// ------------------------- scratch (static device globals; no allocation) ---
__device__ float g_G[(size_t)NB * NB];   // gram matrix F F^T (64 MB)
__device__ float g_t[NB];
__device__ float g_c[NB];
__device__ int   g_pos[NB];
__device__ int   g_neg[NB];
__device__ float g_part[NB];
__device__ __align__(16) uint16_t g_hi[(size_t)NB * ND];  // bf16 hi
__device__ __align__(16) uint16_t g_lo[(size_t)NB * ND];  // bf16 lo

// ------------------------- Threefry-2x32 (20 rounds), JAX-compatible --------
__device__ __forceinline__ uint32_t rotl_d(uint32_t x, int r) {
    return __funnelshift_l(x, x, r);
}
__device__ __forceinline__ void tf_enc(uint32_t k0, uint32_t k1,
                                       uint32_t x0, uint32_t x1,
                                       uint32_t& o0, uint32_t& o1) {
    uint32_t k2 = k0 ^ k1 ^ 0x1BD11BDAu;
    x0 += k0; x1 += k1;
#define TFR(R) { x0 += x1; x1 = rotl_d(x1, R); x1 ^= x0; }
    TFR(13) TFR(15) TFR(26) TFR(6)
    x0 += k1; x1 += k2 + 1u;
    TFR(17) TFR(29) TFR(16) TFR(24)
    x0 += k2; x1 += k0 + 2u;
    TFR(13) TFR(15) TFR(26) TFR(6)
    x0 += k0; x1 += k1 + 3u;
    TFR(17) TFR(29) TFR(16) TFR(24)
    x0 += k1; x1 += k2 + 4u;
    TFR(13) TFR(15) TFR(26) TFR(6)
    x0 += k2; x1 += k0 + 5u;
#undef TFR
    o0 = x0; o1 = x1;
}
static inline uint32_t rotl_h(uint32_t x, int r) { return (x << r) | (x >> (32 - r)); }
static void tf_enc_host(uint32_t k0, uint32_t k1, uint32_t x0, uint32_t x1,
                        uint32_t& o0, uint32_t& o1) {
    uint32_t k2 = k0 ^ k1 ^ 0x1BD11BDAu;
    x0 += k0; x1 += k1;
#define TFRH(R) { x0 += x1; x1 = rotl_h(x1, R); x1 ^= x0; }
    TFRH(13) TFRH(15) TFRH(26) TFRH(6)
    x0 += k1; x1 += k2 + 1u;
    TFRH(17) TFRH(29) TFRH(16) TFRH(24)
    x0 += k2; x1 += k0 + 2u;
    TFRH(13) TFRH(15) TFRH(26) TFRH(6)
    x0 += k0; x1 += k1 + 3u;
    TFRH(17) TFRH(29) TFRH(16) TFRH(24)
    x0 += k1; x1 += k2 + 4u;
    TFRH(13) TFRH(15) TFRH(26) TFRH(6)
    x0 += k2; x1 += k0 + 5u;
#undef TFRH
    o0 = x0; o1 = x1;
}

// ------------------------- sampling kernel ----------------------------------
__global__ void __launch_bounds__(256) k_sample(const int* __restrict__ labels,
                                                uint32_t k1a, uint32_t k1b,
                                                uint32_t k2a, uint32_t k2b) {
    __shared__ int slab[NB];
    __shared__ unsigned long long redn[8], redp[8];
    const int i = blockIdx.x;
    for (int t = threadIdx.x * 4; t < NB; t += blockDim.x * 4)
        *(int4*)&slab[t] = *(const int4*)&labels[t];
    __syncthreads();
    const int Li = slab[i];
    const uint32_t base = (uint32_t)i << 12;

    unsigned long long bestn = 0ull, bestp = 0ull;
    for (int j = threadIdx.x; j < NB; j += blockDim.x) {
        uint32_t o0, o1;
        tf_enc(k2a, k2b, 0u, base + (uint32_t)j, o0, o1);
        uint32_t v = ((o0 ^ o1) >> 9) + 1u;
        unsigned long long cand =
            ((unsigned long long)v << 12) | (uint32_t)(4095 - j);
        if (slab[j] != Li) {
            if (cand > bestn) bestn = cand;
        } else {
            uint32_t p0, p1;
            tf_enc(k1a, k1b, 0u, base + (uint32_t)j, p0, p1);
            uint32_t vp = ((p0 ^ p1) >> 9) + 1u;
            unsigned long long candp =
                ((unsigned long long)vp << 12) | (uint32_t)(4095 - j);
            if (candp > bestp) bestp = candp;
        }
    }
    for (int off = 16; off; off >>= 1) {
        unsigned long long a = __shfl_down_sync(0xffffffffu, bestn, off);
        unsigned long long b = __shfl_down_sync(0xffffffffu, bestp, off);
        if (a > bestn) bestn = a;
        if (b > bestp) bestp = b;
    }
    const int warp = threadIdx.x >> 5, lane = threadIdx.x & 31;
    if (lane == 0) { redn[warp] = bestn; redp[warp] = bestp; }
    __syncthreads();
    if (threadIdx.x == 0) {
        unsigned long long bn = 0ull, bp = 0ull;
        for (int w = 0; w < 8; w++) {
            if (redn[w] > bn) bn = redn[w];
            if (redp[w] > bp) bp = redp[w];
        }
        g_neg[i] = 4095 - (int)(bn & 0xFFFu);
        g_pos[i] = 4095 - (int)(bp & 0xFFFu);
    }
}

// ------------------------- row norms / sums ---------------------------------
__global__ void __launch_bounds__(256) k_norms(const float* __restrict__ F) {
    const int i = blockIdx.x;
    const float4* row = (const float4*)(F + (size_t)i * ND);
    float n2 = 0.f, s = 0.f;
    for (int k = threadIdx.x; k < ND / 4; k += blockDim.x) {
        float4 v = row[k];
        n2 = fmaf(v.x, v.x, fmaf(v.y, v.y, fmaf(v.z, v.z, fmaf(v.w, v.w, n2))));
        s += (v.x + v.y) + (v.z + v.w);
    }
    for (int off = 16; off; off >>= 1) {
        n2 += __shfl_down_sync(0xffffffffu, n2, off);
        s  += __shfl_down_sync(0xffffffffu, s,  off);
    }
    __shared__ float sn[8], ss[8];
    const int warp = threadIdx.x >> 5, lane = threadIdx.x & 31;
    if (lane == 0) { sn[warp] = n2; ss[warp] = s; }
    __syncthreads();
    if (threadIdx.x == 0) {
        float a = 0.f, b = 0.f;
        for (int w = 0; w < 8; w++) { a += sn[w]; b += ss[w]; }
        g_t[i] = a + 2.f * F_EPS * b + (float)ND * F_EPS * F_EPS;
        g_c[i] = a - 2.f * F_EPS * b;
    }
}

// ------------------------- bf16 hi/lo split (row-major) ---------------------
__global__ void __launch_bounds__(256) k_split(const float* __restrict__ F) {
    const int idx = blockIdx.x * 256 + threadIdx.x;   // 0..524287, 8 floats each
    const size_t e0 = (size_t)idx * 8;
    const float4* src = (const float4*)(F + e0);
    float4 v0 = src[0], v1 = src[1];
    float x[8] = {v0.x, v0.y, v0.z, v0.w, v1.x, v1.y, v1.z, v1.w};
    uint16_t h[8], l[8];
#pragma unroll
    for (int e = 0; e < 8; e++) {
        __nv_bfloat16 hb = __float2bfloat16(x[e]);
        __nv_bfloat16 lb = __float2bfloat16(x[e] - __bfloat162float(hb));
        h[e] = *(uint16_t*)&hb;
        l[e] = *(uint16_t*)&lb;
    }
    *(uint4*)(g_hi + e0) = *(const uint4*)h;
    *(uint4*)(g_lo + e0) = *(const uint4*)l;
}

// ------------------------- mma.sync GEMM helpers ----------------------------
__device__ __forceinline__ uint32_t smem_u32(const void* p) {
    uint32_t a;
    asm("{ .reg .u64 t; cvta.to.shared.u64 t, %1; cvt.u32.u64 %0, t; }"
        : "=r"(a) : "l"(p));
    return a;
}
#define LDSM4(r0, r1, r2, r3, addr)                                          \
    asm volatile("ldmatrix.sync.aligned.m8n8.x4.shared.b16 {%0,%1,%2,%3}, [%4];" \
                 : "=r"(r0), "=r"(r1), "=r"(r2), "=r"(r3) : "r"(addr))
#define MMA16816(c, a0, a1, a2, a3, b0, b1)                                  \
    asm volatile("mma.sync.aligned.m16n8k16.row.col.f32.bf16.bf16.f32 "      \
                 "{%0,%1,%2,%3}, {%4,%5,%6,%7}, {%8,%9}, {%0,%1,%2,%3};"     \
                 : "+f"((c)[0]), "+f"((c)[1]), "+f"((c)[2]), "+f"((c)[3])    \
                 : "r"(a0), "r"(a1), "r"(a2), "r"(a3), "r"(b0), "r"(b1))
#define CP16(saddr, gptr)                                                    \
    asm volatile("cp.async.cg.shared.global [%0], [%1], 16;"                 \
                 :: "r"(saddr), "l"(gptr) : "memory")

// smem stage layout: 4 tiles of 8192 B (Ahi, Alo, Bhi, Blo), 3 stages.
// Each tile: 128 rows x 64 B (32 bf16), 16B chunks swizzled c' = c ^ ((m>>1)&3).
#define STAGE_BYTES 32768
#define TILE_BYTES  8192
#define DSM_BYTES   98304   // 3 stages; also covers 128x132 transpose (67584)

// ------------------------- tensor-core GEMM: G = F F^T ----------------------
__global__ void __launch_bounds__(256, 2) k_gemm_mma() {
    // triangle decode: bid -> (bx, by), by <= bx
    int bid = blockIdx.x;
    int bx = (int)((sqrt(8.0 * (double)bid + 1.0) - 1.0) * 0.5);
    while ((bx + 1) * (bx + 2) / 2 <= bid) bx++;
    while (bx * (bx + 1) / 2 > bid) bx--;
    int by = bid - bx * (bx + 1) / 2;

    extern __shared__ char dsm[];
    const uint32_t smemBase = smem_u32(dsm);
    const int tid = threadIdx.x;
    const int lane = tid & 31, wid = tid >> 5;
    const int wm = wid >> 2, wn = wid & 3;   // warp tile: 64(m) x 32(n)

    const uint16_t* gsrc[4];
    gsrc[0] = g_hi + (size_t)(bx * 128) * ND;
    gsrc[1] = g_lo + (size_t)(bx * 128) * ND;
    gsrc[2] = g_hi + (size_t)(by * 128) * ND;
    gsrc[3] = g_lo + (size_t)(by * 128) * ND;

    float acc[4][4][4];
#pragma unroll
    for (int a = 0; a < 4; a++)
#pragma unroll
        for (int b = 0; b < 4; b++)
#pragma unroll
            for (int c = 0; c < 4; c++) acc[a][b][c] = 0.f;

#define LOAD_STAGE(S, KT)                                                     \
    {                                                                         \
        _Pragma("unroll")                                                     \
        for (int i = 0; i < 8; i++) {                                         \
            int idx = tid + i * 256;                                          \
            int tile = idx >> 9;                                              \
            int m = (idx >> 2) & 127;                                         \
            int c = idx & 3;                                                  \
            const uint16_t* gp = gsrc[tile] + (size_t)m * ND + (KT) + c * 8;  \
            uint32_t sa = smemBase + (S) * STAGE_BYTES + tile * TILE_BYTES +  \
                          m * 64 + ((c ^ ((m >> 1) & 3)) * 16);               \
            CP16(sa, gp);                                                     \
        }                                                                     \
    }

    LOAD_STAGE(0, 0)
    asm volatile("cp.async.commit_group;" ::: "memory");
    LOAD_STAGE(1, 32)
    asm volatile("cp.async.commit_group;" ::: "memory");

    const int r15 = lane & 15, kh = lane >> 4;

#pragma unroll 1
    for (int kc = 0; kc < 32; kc++) {
        asm volatile("cp.async.wait_group 1;" ::: "memory");
        __syncthreads();
        // prefetch stage kc+2 (buffer last read in iter kc-1; safe after sync)
        if (kc + 2 < 32) LOAD_STAGE((kc + 2) % 3, (kc + 2) * 32)
        asm volatile("cp.async.commit_group;" ::: "memory");

        const uint32_t sb = smemBase + (uint32_t)(kc % 3) * STAGE_BYTES;
        const uint32_t aH = sb, aL = sb + TILE_BYTES;
        const uint32_t bH = sb + 2 * TILE_BYTES, bL = sb + 3 * TILE_BYTES;

#pragma unroll
        for (int k16 = 0; k16 < 2; k16++) {
            const int cIdx = k16 * 2 + kh;
            uint32_t bh[4][2], bl[4][2];
#pragma unroll
            for (int bt = 0; bt < 2; bt++) {
                int n = wn * 32 + bt * 16 + r15;
                uint32_t cp = (uint32_t)(cIdx ^ ((n >> 1) & 3));
                uint32_t r0, r1, r2, r3;
                LDSM4(r0, r1, r2, r3, bH + n * 64 + cp * 16);
                bh[bt * 2][0] = r0; bh[bt * 2 + 1][0] = r1;
                bh[bt * 2][1] = r2; bh[bt * 2 + 1][1] = r3;
                LDSM4(r0, r1, r2, r3, bL + n * 64 + cp * 16);
                bl[bt * 2][0] = r0; bl[bt * 2 + 1][0] = r1;
                bl[bt * 2][1] = r2; bl[bt * 2 + 1][1] = r3;
            }
#pragma unroll
            for (int mt = 0; mt < 4; mt++) {
                int m = wm * 64 + mt * 16 + r15;
                uint32_t cp = (uint32_t)(cIdx ^ ((m >> 1) & 3));
                uint32_t a0, a1, a2, a3;
                LDSM4(a0, a1, a2, a3, aH + m * 64 + cp * 16);
#pragma unroll
                for (int nt = 0; nt < 4; nt++)
                    MMA16816(acc[mt][nt], a0, a1, a2, a3, bh[nt][0], bh[nt][1]);
#pragma unroll
                for (int nt = 0; nt < 4; nt++)
                    MMA16816(acc[mt][nt], a0, a1, a2, a3, bl[nt][0], bl[nt][1]);
                LDSM4(a0, a1, a2, a3, aL + m * 64 + cp * 16);
#pragma unroll
                for (int nt = 0; nt < 4; nt++)
                    MMA16816(acc[mt][nt], a0, a1, a2, a3, bh[nt][0], bh[nt][1]);
            }
        }
    }

    // ---------------- epilogue: direct tile + mirror via smem transpose -----
    const int r0 = bx * 128, c0 = by * 128;
    const int qr = lane >> 2, qc = 2 * (lane & 3);
#pragma unroll
    for (int mt = 0; mt < 4; mt++)
#pragma unroll
        for (int nt = 0; nt < 4; nt++) {
            int row = r0 + wm * 64 + mt * 16 + qr;
            int col = c0 + wn * 32 + nt * 8 + qc;
            float2 v01 = make_float2(acc[mt][nt][0], acc[mt][nt][1]);
            float2 v23 = make_float2(acc[mt][nt][2], acc[mt][nt][3]);
            *(float2*)&g_G[(size_t)row * NB + col] = v01;
            *(float2*)&g_G[(size_t)(row + 8) * NB + col] = v23;
        }

    if (bx != by) {
        float (*sT)[132] = (float (*)[132])dsm;   // [n][m], 128x132 floats
        __syncthreads();   // compute buffers dead; reuse smem
#pragma unroll
        for (int mt = 0; mt < 4; mt++)
#pragma unroll
            for (int nt = 0; nt < 4; nt++) {
                int rl = wm * 64 + mt * 16 + qr;
                int cl = wn * 32 + nt * 8 + qc;
                sT[cl][rl]         = acc[mt][nt][0];
                sT[cl + 1][rl]     = acc[mt][nt][1];
                sT[cl][rl + 8]     = acc[mt][nt][2];
                sT[cl + 1][rl + 8] = acc[mt][nt][3];
            }
        __syncthreads();
#pragma unroll
        for (int e = tid * 4; e < 128 * 128; e += 256 * 4) {
            int n = e >> 7, m = e & 127;
            float4 v = *(float4*)&sT[n][m];
            *(float4*)&g_G[(size_t)(c0 + n) * NB + r0 + m] = v;
        }
    }
#undef LOAD_STAGE
}

// ------------------------- loss reduction -----------------------------------
__device__ __forceinline__ float pairterm(float t, float gp, float gq,
                                          float cp, float cq) {
    float sap = fmaxf(fmaf(-2.f, gp, t + cp), 1e-12f);
    float san = fmaxf(fmaf(-2.f, gq, t + cq), 1e-12f);
    float dap, dan;
    asm("sqrt.approx.f32 %0, %1;" : "=f"(dap) : "f"(sap));
    asm("sqrt.approx.f32 %0, %1;" : "=f"(dan) : "f"(san));
    return fmaxf(dap - dan + F_MARGIN, 0.f);
}

__global__ void __launch_bounds__(256) k_loss() {
    const int i = blockIdx.x;
    const int p = g_pos[i], q = g_neg[i];
    const float cp = g_c[p], cq = g_c[q];
    const float4* Gp = (const float4*)(g_G + (size_t)p * NB);
    const float4* Gq = (const float4*)(g_G + (size_t)q * NB);
    const float4* T  = (const float4*)g_t;
    float acc = 0.f;
    for (int j = threadIdx.x; j < NB / 4; j += blockDim.x) {
        float4 gp = Gp[j], gq = Gq[j], tt = T[j];
        acc += pairterm(tt.x, gp.x, gq.x, cp, cq);
        acc += pairterm(tt.y, gp.y, gq.y, cp, cq);
        acc += pairterm(tt.z, gp.z, gq.z, cp, cq);
        acc += pairterm(tt.w, gp.w, gq.w, cp, cq);
    }
    for (int off = 16; off; off >>= 1)
        acc += __shfl_down_sync(0xffffffffu, acc, off);
    __shared__ float sa[8];
    const int warp = threadIdx.x >> 5, lane = threadIdx.x & 31;
    if (lane == 0) sa[warp] = acc;
    __syncthreads();
    if (threadIdx.x == 0) {
        float s = 0.f;
        for (int w = 0; w < 8; w++) s += sa[w];
        g_part[i] = s;
    }
}

__global__ void __launch_bounds__(256) k_final(float* __restrict__ out) {
    __shared__ double sm[256];
    double a = 0.0;
    for (int i = threadIdx.x; i < NB; i += 256) a += (double)g_part[i];
    sm[threadIdx.x] = a;
    __syncthreads();
    for (int s = 128; s; s >>= 1) {
        if (threadIdx.x < s) sm[threadIdx.x] += sm[threadIdx.x + s];
        __syncthreads();
    }
    if (threadIdx.x == 0)
        out[0] = (float)(sm[0] / (double)((size_t)NB * NB));
}

// ------------------------- launch -------------------------------------------
extern "C" void kernel_launch(void* const* d_in, const int* in_sizes, int n_in,
                              void* d_out, int out_size) {
    const float* F = (const float*)d_in[0];
    const int* labels = (const int*)d_in[1];
    float* out = (float*)d_out;

    uint32_t k1a, k1b, k2a, k2b;
    tf_enc_host(0u, 42u, 0u, 0u, k1a, k1b);
    tf_enc_host(0u, 42u, 0u, 1u, k2a, k2b);

    static int smem_set = 0;
    if (!smem_set) {
        cudaFuncSetAttribute(k_gemm_mma,
                             cudaFuncAttributeMaxDynamicSharedMemorySize,
                             DSM_BYTES);
        smem_set = 1;
    }

    k_split<<<2048, 256>>>(F);
    k_sample<<<NB, 256>>>(labels, k1a, k1b, k2a, k2b);
    k_norms<<<NB, 256>>>(F);
    k_gemm_mma<<<528, 256, DSM_BYTES>>>();
    k_loss<<<NB, 256>>>();
    k_final<<<1, 256>>>(out);
}